// round 12
// baseline (speedup 1.0000x reference)
#include <cuda_runtime.h>
#include <cuda_fp16.h>
#include <cstdint>

#define B      64
#define PP     196
#define ENC    2048
#define LCAP   32
#define V      20000
#define ATT    512
#define EMB    512
#define DEC    512
#define TSTEPS 31
#define XDIM   (EMB+ENC)   /* 2560 */
#define G4     (4*DEC)     /* 2048 */
#define NH     (B*TSTEPS)  /* 1984 */
#define HPN    (ATT+ENC+G4) /* 4608 */
#define HPS    ((size_t)B*HPN)
#define GS     ((size_t)B*G4)

// ---------------- device scratch ----------------
__device__ __half g_att1h[(size_t)B*PP*ATT];
__device__ __half g_ench[(size_t)B*PP*ENC];
__device__ __half g_fcWh[(size_t)V*DEC];
__device__ __half g_Whph[(size_t)HPN*DEC];      // [Wda;Wbeta;Whh] fp16
__device__ __half g_Wihh[(size_t)G4*ENC];       // W_ih[:,512:] fp16
__device__ __half g_Wihe[(size_t)G4*EMB];       // W_ih[:,:512] fp16
__device__ __half g_Weah[(size_t)ATT*ENC];      // W_enc_att fp16
__device__ __half g_embh[(size_t)V*EMB];        // emb_table fp16
__device__ __half g_hh[B*DEC];                  // h state fp16
__device__ __half g_hhist[(size_t)NH*DEC];      // h history (zero-init)
__device__ __half g_xeh[B*ENC];                 // gate*awe fp16
__device__ float  g_mean[B*ENC];
__device__ float  g_c[B*DEC];                   // c state fp32 exact
__device__ float  g_hppart[2*HPS];              // hproj split-K partials
__device__ float  g_gpart[8*GS];                // gates split-K partials
__device__ float  g_eg[(size_t)NH*G4];
__device__ float  g_ipart[4*64*1024];
__device__ int    g_bact[TSTEPS];

__device__ __forceinline__ float sigmoidf_(float x){ return 1.0f/(1.0f+expf(-x)); }
__device__ __forceinline__ void mma_f16(float* d, uint32_t a0, uint32_t a1, uint32_t a2, uint32_t a3,
                                        uint32_t b0, uint32_t b1){
  asm volatile("mma.sync.aligned.m16n8k16.row.col.f32.f16.f16.f32 "
    "{%0,%1,%2,%3},{%4,%5,%6,%7},{%8,%9},{%0,%1,%2,%3};"
    : "+f"(d[0]),"+f"(d[1]),"+f"(d[2]),"+f"(d[3])
    : "r"(a0),"r"(a1),"r"(a2),"r"(a3),"r"(b0),"r"(b1));
}

// ---------------- one-time kernels ----------------
__global__ void k_bact(const int* __restrict__ caplen){
  int t = threadIdx.x;
  if (t < TSTEPS){
    int c = 0;
    for (int b=0;b<B;b++) c += ((caplen[b]-1) > t) ? 1 : 0;
    g_bact[t] = c;
  }
}

__global__ void k_cvtmean(const float* __restrict__ enc){
  int b = blockIdx.x;
  int e = blockIdx.y*256 + threadIdx.x;
  const float* p0 = enc + (size_t)b*PP*ENC + e;
  __half* h0 = g_ench + (size_t)b*PP*ENC + e;
  float s = 0.f;
  #pragma unroll 4
  for (int p=0;p<PP;p++){
    float v = p0[(size_t)p*ENC];
    s += v;
    h0[(size_t)p*ENC] = __float2half_rn(v);
  }
  g_mean[b*ENC + e] = s * (1.0f/PP);
}

__global__ void k_cvtfcw(const float* __restrict__ W){
  size_t i = (size_t)blockIdx.x*blockDim.x + threadIdx.x;
  const size_t n4 = (size_t)V*DEC/4;
  if (i >= n4) return;
  float4 v = ((const float4*)W)[i];
  __half2* o = (__half2*)g_fcWh;
  o[i*2]   = __floats2half2_rn(v.x, v.y);
  o[i*2+1] = __floats2half2_rn(v.z, v.w);
}

__global__ void k_cvtweah(const float* __restrict__ W){
  size_t i = (size_t)blockIdx.x*blockDim.x + threadIdx.x;
  const size_t n4 = (size_t)ATT*ENC/4;
  if (i >= n4) return;
  float4 v = ((const float4*)W)[i];
  __half2* o = (__half2*)g_Weah;
  o[i*2]   = __floats2half2_rn(v.x, v.y);
  o[i*2+1] = __floats2half2_rn(v.z, v.w);
}

__global__ void k_cvtembh(const float* __restrict__ E){
  size_t i = (size_t)blockIdx.x*blockDim.x + threadIdx.x;
  const size_t n4 = (size_t)V*EMB/4;
  if (i >= n4) return;
  float4 v = ((const float4*)E)[i];
  __half2* o = (__half2*)g_embh;
  o[i*2]   = __floats2half2_rn(v.x, v.y);
  o[i*2+1] = __floats2half2_rn(v.z, v.w);
}

__global__ void k_cvthp(const float* __restrict__ Wda, const float* __restrict__ Wbeta,
                        const float* __restrict__ Whh){
  size_t i = (size_t)blockIdx.x*blockDim.x + threadIdx.x;
  const size_t n4 = (size_t)HPN*DEC/4;
  if (i >= n4) return;
  size_t el = i*4;
  int row = (int)(el / DEC), col = (int)(el % DEC);
  const float* src;
  if (row < ATT)          src = Wda   + (size_t)row*DEC;
  else if (row < ATT+ENC) src = Wbeta + (size_t)(row-ATT)*DEC;
  else                    src = Whh   + (size_t)(row-ATT-ENC)*DEC;
  float4 v = *(const float4*)(src + col);
  __half2* o = (__half2*)(g_Whph + el);
  o[0] = __floats2half2_rn(v.x, v.y);
  o[1] = __floats2half2_rn(v.z, v.w);
}

__global__ void k_cvtwih(const float* __restrict__ Wih){
  size_t i = (size_t)blockIdx.x*blockDim.x + threadIdx.x;
  const size_t n4 = (size_t)G4*XDIM/4;
  if (i >= n4) return;
  size_t el = i*4;
  int row = (int)(el / XDIM), col = (int)(el % XDIM);
  float4 v = *(const float4*)(Wih + el);
  __half2 h0 = __floats2half2_rn(v.x, v.y);
  __half2 h1 = __floats2half2_rn(v.z, v.w);
  if (col < EMB){
    __half2* o = (__half2*)(g_Wihe + (size_t)row*EMB + col);
    o[0]=h0; o[1]=h1;
  } else {
    __half2* o = (__half2*)(g_Wihh + (size_t)row*ENC + (col-EMB));
    o[0]=h0; o[1]=h1;
  }
}

__global__ void k_init(const float* __restrict__ Wh, const float* __restrict__ Wc){
  __shared__ float sA[32][68];
  __shared__ float sW[32][34];
  int tid = threadIdx.x, tx = tid & 15, ty = tid >> 4;
  int gn0 = blockIdx.x * 32;
  int ks  = blockIdx.z;
  const float* Wp = (gn0 < DEC) ? (Wh + (size_t)gn0*ENC) : (Wc + (size_t)(gn0-DEC)*ENC);
  float acc[4][2] = {};
  for (int k0=ks*512; k0<ks*512+512; k0+=32){
    #pragma unroll
    for (int i=0;i<2;i++){
      int lin = tid + i*256, row = lin >> 3, kq = lin & 7;
      float4 v = *(const float4*)(g_mean + row*ENC + k0 + kq*4);
      sA[kq*4+0][row]=v.x; sA[kq*4+1][row]=v.y; sA[kq*4+2][row]=v.z; sA[kq*4+3][row]=v.w;
    }
    {
      int n = tid >> 3, kq = tid & 7;
      float4 v = *(const float4*)(Wp + (size_t)n*ENC + k0 + kq*4);
      sW[kq*4+0][n]=v.x; sW[kq*4+1][n]=v.y; sW[kq*4+2][n]=v.z; sW[kq*4+3][n]=v.w;
    }
    __syncthreads();
    #pragma unroll
    for (int k=0;k<32;k++){
      float4 a = *(const float4*)&sA[k][ty*4];
      float2 w = *(const float2*)&sW[k][tx*2];
      acc[0][0]+=a.x*w.x; acc[0][1]+=a.x*w.y;
      acc[1][0]+=a.y*w.x; acc[1][1]+=a.y*w.y;
      acc[2][0]+=a.z*w.x; acc[2][1]+=a.z*w.y;
      acc[3][0]+=a.w*w.x; acc[3][1]+=a.w*w.y;
    }
    __syncthreads();
  }
  #pragma unroll
  for (int i=0;i<4;i++){
    int m = ty*4+i;
    #pragma unroll
    for (int j=0;j<2;j++)
      g_ipart[(size_t)ks*64*1024 + m*1024 + gn0 + tx*2 + j] = acc[i][j];
  }
}

__global__ void k_init_red(const float* __restrict__ bh, const float* __restrict__ bc){
  int m = blockIdx.x;
  for (int c=threadIdx.x; c<1024; c+=256){
    float v = g_ipart[m*1024+c] + g_ipart[64*1024 + m*1024+c]
            + g_ipart[2*64*1024 + m*1024+c] + g_ipart[3*64*1024 + m*1024+c];
    if (c < DEC) g_hh[m*DEC + c]      = __float2half_rn(v + bh[c]);
    else         g_c[m*DEC + (c-DEC)] = v + bc[c-DEC];
  }
}

// ---------------- fp16 mma core, double-buffered (M=64, BN=128) ----------------
// buffers: sA[2][64*20], sW[2][128*20] (half2). One __syncthreads per 32-K slab.
template<int KLEN>
__device__ __forceinline__ void tc16_core(__half2* sbuf,
    const __half* Ap, const __half* Wp0, const __half* Wp1, float acc[8][4]){
  __half2* sA0 = sbuf;
  __half2* sW0 = sbuf + 2*64*20;
  const int AS = 64*20, WS = 128*20;
  int tid=threadIdx.x, lane=tid&31, wp=tid>>5;
  int mr=wp>>1, nc=wp&1;
  int lr=tid>>2, kq8=(tid&3)*8;
  int r = mr*16 + (lane>>2);
  int cq = lane&3;
  uint4 a  = *(const uint4*)(Ap + kq8);
  uint4 w0 = *(const uint4*)(Wp0 + kq8);
  uint4 w1 = *(const uint4*)(Wp1 + kq8);
  *(uint4*)(sA0 + lr*20 + kq8/2)      = a;
  *(uint4*)(sW0 + lr*20 + kq8/2)      = w0;
  *(uint4*)(sW0 + (lr+64)*20 + kq8/2) = w1;
  __syncthreads();
  for (int k0=0;k0<KLEN;k0+=32){
    int cur = (k0>>5)&1;
    __half2* cA = sA0 + cur*AS;
    __half2* cW = sW0 + cur*WS;
    if (k0+32<KLEN){
      a  = *(const uint4*)(Ap + k0+32 + kq8);
      w0 = *(const uint4*)(Wp0 + k0+32 + kq8);
      w1 = *(const uint4*)(Wp1 + k0+32 + kq8);
      __half2* nA = sA0 + (cur^1)*AS;
      __half2* nW = sW0 + (cur^1)*WS;
      *(uint4*)(nA + lr*20 + kq8/2)      = a;
      *(uint4*)(nW + lr*20 + kq8/2)      = w0;
      *(uint4*)(nW + (lr+64)*20 + kq8/2) = w1;
    }
    #pragma unroll
    for (int kk=0;kk<2;kk++){
      int o = kk*8 + cq;
      uint32_t a0=*(uint32_t*)(cA + r*20 + o);
      uint32_t a1=*(uint32_t*)(cA + (r+8)*20 + o);
      uint32_t a2=*(uint32_t*)(cA + r*20 + o+4);
      uint32_t a3=*(uint32_t*)(cA + (r+8)*20 + o+4);
      #pragma unroll
      for (int j=0;j<8;j++){
        int n = nc*64 + j*8 + (lane>>2);
        uint32_t b0=*(uint32_t*)(cW + n*20 + o);
        uint32_t b1=*(uint32_t*)(cW + n*20 + o+4);
        mma_f16(acc[j], a0, a1, a2, a3, b0, b1);
      }
    }
    __syncthreads();
  }
}
#define SBUF_H2 (2*(64*20 + 128*20))
#define ACC_INIT(acc) { _Pragma("unroll") for (int j=0;j<8;j++){ acc[j][0]=acc[j][1]=acc[j][2]=acc[j][3]=0.f; } }

// one-time: att1 = ench @ W_enc_att^T + bias (fp16 mma). grid (4, 196)
__global__ void __launch_bounds__(256) k_att1(const float* __restrict__ bias){
  __shared__ __align__(16) __half2 sbuf[SBUF_H2];
  int m0 = blockIdx.y*64, gn0 = blockIdx.x*128;
  int tid=threadIdx.x, lane=tid&31, wp=tid>>5;
  int mr=wp>>1, nc=wp&1, lr=tid>>2;
  float acc[8][4]; ACC_INIT(acc)
  tc16_core<ENC>(sbuf,
                 g_ench + (size_t)(m0+lr)*ENC,
                 g_Weah + (size_t)(gn0+lr)*ENC,
                 g_Weah + (size_t)(gn0+lr+64)*ENC, acc);
  int r0=m0+mr*16+(lane>>2), c0=(lane&3)*2;
  #pragma unroll
  for (int j=0;j<8;j++){
    int gn=gn0+nc*64+j*8+c0;
    *(__half2*)(g_att1h + (size_t)r0*ATT + gn)     = __floats2half2_rn(acc[j][0]+bias[gn], acc[j][1]+bias[gn+1]);
    *(__half2*)(g_att1h + (size_t)(r0+8)*ATT + gn) = __floats2half2_rn(acc[j][2]+bias[gn], acc[j][3]+bias[gn+1]);
  }
}

// one-time: g_eg = emb[tok] @ W_ih[:, :512]^T (fp16 mma). grid (16, 31)
__global__ void __launch_bounds__(256) k_embgate(const int* __restrict__ caps){
  __shared__ __align__(16) __half2 sbuf[SBUF_H2];
  int m0 = blockIdx.y*64, gn0 = blockIdx.x*128;
  int tid=threadIdx.x, lane=tid&31, wp=tid>>5;
  int mr=wp>>1, nc=wp&1, lr=tid>>2;
  int gr = m0 + lr;
  int tok = caps[(gr/TSTEPS)*LCAP + (gr%TSTEPS)];
  float acc[8][4]; ACC_INIT(acc)
  tc16_core<EMB>(sbuf,
                 g_embh + (size_t)tok*EMB,
                 g_Wihe + (size_t)(gn0+lr)*EMB,
                 g_Wihe + (size_t)(gn0+lr+64)*EMB, acc);
  int r0=m0+mr*16+(lane>>2), c0=(lane&3)*2;
  #pragma unroll
  for (int j=0;j<8;j++){
    int gn=gn0+nc*64+j*8+c0;
    g_eg[(size_t)r0*G4 + gn]       = acc[j][0];
    g_eg[(size_t)r0*G4 + gn+1]     = acc[j][1];
    g_eg[(size_t)(r0+8)*G4 + gn]   = acc[j][2];
    g_eg[(size_t)(r0+8)*G4 + gn+1] = acc[j][3];
  }
}

// ---------------- per-step kernels ----------------
// ph1: hproj [Wda;Wbeta] only (att2+gatepre), split-K2: 40 tiles; tile = ks*20 + nt
__global__ void __launch_bounds__(256) k_ph1(int t){
  (void)t;
  __shared__ __align__(16) __half2 sbuf[SBUF_H2];
  int tile = blockIdx.x;
  int nt = tile % 20, ks = tile / 20;
  int gn0 = nt*128, kofs = ks*256;
  int tid=threadIdx.x, lane=tid&31, wp=tid>>5;
  int mr=wp>>1, nc=wp&1, lr=tid>>2;
  float acc[8][4]; ACC_INIT(acc)
  tc16_core<256>(sbuf,
                 g_hh + lr*DEC + kofs,
                 g_Whph + (size_t)(gn0+lr)*DEC + kofs,
                 g_Whph + (size_t)(gn0+lr+64)*DEC + kofs, acc);
  int r0=mr*16+(lane>>2), c0=(lane&3)*2;
  float* out = g_hppart + (size_t)ks*HPS;
  #pragma unroll
  for (int j=0;j<8;j++){
    int gn=gn0+nc*64+j*8+c0;
    out[(size_t)r0*HPN + gn]       = acc[j][0];
    out[(size_t)r0*HPN + gn+1]     = acc[j][1];
    out[(size_t)(r0+8)*HPN + gn]   = acc[j][2];
    out[(size_t)(r0+8)*HPN + gn+1] = acc[j][3];
  }
}

// ph2: alpha+awe, one block of 512 threads per b
__global__ void __launch_bounds__(512) k_ph2(
    const float* __restrict__ b_dec_att, const float* __restrict__ w_full,
    const float* __restrict__ b_full, const float* __restrict__ b_beta,
    float* __restrict__ alphas, int t){
  int b = blockIdx.x, tid = threadIdx.x;
  int nact = g_bact[t];
  if (b >= nact){
    for (int p=tid;p<PP;p+=512) alphas[(size_t)b*TSTEPS*PP + (size_t)t*PP + p] = 0.f;
    return;
  }
  __shared__ float s_a2[ATT];
  __shared__ float s_wf[ATT];
  __shared__ float s_e[200];
  __shared__ float s_red[16];
  const float* hp0 = g_hppart + (size_t)b*HPN;
  const float* hp1 = g_hppart + HPS + (size_t)b*HPN;
  for (int a=tid;a<ATT;a+=512){
    s_a2[a] = hp0[a] + hp1[a] + b_dec_att[a];
    s_wf[a] = w_full[a];
  }
  __syncthreads();
  int warp = tid>>5, lane = tid&31;
  float bf = b_full[0];
  for (int p=warp; p<PP; p+=16){
    const __half2* r = (const __half2*)(g_att1h + (size_t)(b*PP+p)*ATT);
    float s=0.f;
    #pragma unroll
    for (int i=0;i<8;i++){
      int a2i = lane + i*32;
      float2 f = __half22float2(r[a2i]);
      int a = a2i*2;
      s += fmaxf(f.x + s_a2[a],0.f)*s_wf[a] + fmaxf(f.y + s_a2[a+1],0.f)*s_wf[a+1];
    }
    #pragma unroll
    for (int o=16;o;o>>=1) s += __shfl_xor_sync(0xffffffffu,s,o);
    if (lane==0) s_e[p] = s + bf;
  }
  __syncthreads();
  float m = (tid < PP) ? s_e[tid] : -1e30f;
  #pragma unroll
  for (int o=16;o;o>>=1) m = fmaxf(m,__shfl_xor_sync(0xffffffffu,m,o));
  if (lane==0) s_red[warp]=m;
  __syncthreads();
  float mx = s_red[0];
  #pragma unroll
  for (int i=1;i<16;i++) mx = fmaxf(mx, s_red[i]);
  __syncthreads();
  float sum = 0.f;
  if (tid < PP){ float ex = expf(s_e[tid]-mx); s_e[tid]=ex; sum=ex; }
  #pragma unroll
  for (int o=16;o;o>>=1) sum += __shfl_xor_sync(0xffffffffu,sum,o);
  if (lane==0) s_red[warp]=sum;
  __syncthreads();
  float tot = 0.f;
  #pragma unroll
  for (int i=0;i<16;i++) tot += s_red[i];
  float inv = 1.0f/tot;
  if (tid < PP){
    float al = s_e[tid]*inv;
    s_e[tid] = al;
    alphas[(size_t)b*TSTEPS*PP + (size_t)t*PP + tid] = al;
  }
  __syncthreads();
  const __half2* eb = (const __half2*)g_ench + (size_t)b*PP*(ENC/2);
  int c0 = tid, c1 = tid + 512;
  float ax=0.f, ay=0.f, cx=0.f, cy=0.f;
  #pragma unroll 2
  for (int p=0;p<PP;p++){
    float al = s_e[p];
    float2 f0 = __half22float2(eb[(size_t)p*(ENC/2) + c0]);
    float2 f1 = __half22float2(eb[(size_t)p*(ENC/2) + c1]);
    ax += al*f0.x; ay += al*f0.y;
    cx += al*f1.x; cy += al*f1.y;
  }
  int e = c0*2;
  float g0 = sigmoidf_(hp0[ATT+e]   + hp1[ATT+e]   + b_beta[e]);
  float g1 = sigmoidf_(hp0[ATT+e+1] + hp1[ATT+e+1] + b_beta[e+1]);
  *(__half2*)(g_xeh + (size_t)b*ENC + e) = __floats2half2_rn(g0*ax, g1*ay);
  int e2 = c1*2;
  float g2 = sigmoidf_(hp0[ATT+e2]   + hp1[ATT+e2]   + b_beta[e2]);
  float g3 = sigmoidf_(hp0[ATT+e2+1] + hp1[ATT+e2+1] + b_beta[e2+1]);
  *(__half2*)(g_xeh + (size_t)b*ENC + e2) = __floats2half2_rn(g2*cx, g3*cy);
}

// ph3: gates split-K8 (128 tiles) + hWhh split-K2 (32 tiles) = 160 tiles
__global__ void __launch_bounds__(256) k_ph3(int t){
  (void)t;
  __shared__ __align__(16) __half2 sbuf[SBUF_H2];
  int tile = blockIdx.x;
  int tid=threadIdx.x, lane=tid&31, wp=tid>>5;
  int mr=wp>>1, nc=wp&1, lr=tid>>2;
  float acc[8][4]; ACC_INIT(acc)
  if (tile < 128){
    int nt = tile & 15, ks = tile >> 4;
    int gn0 = nt*128, kofs = ks*256;
    tc16_core<256>(sbuf,
                   g_xeh + (size_t)lr*ENC + kofs,
                   g_Wihh + (size_t)(gn0+lr)*ENC + kofs,
                   g_Wihh + (size_t)(gn0+lr+64)*ENC + kofs, acc);
    int r0=mr*16+(lane>>2), c0=(lane&3)*2;
    float* out = g_gpart + (size_t)ks*GS;
    #pragma unroll
    for (int j=0;j<8;j++){
      int gn=gn0+nc*64+j*8+c0;
      out[(size_t)r0*G4 + gn]       = acc[j][0];
      out[(size_t)r0*G4 + gn+1]     = acc[j][1];
      out[(size_t)(r0+8)*G4 + gn]   = acc[j][2];
      out[(size_t)(r0+8)*G4 + gn+1] = acc[j][3];
    }
  } else {
    int i = tile - 128;
    int nt = i & 15, ks = i >> 4;
    int gn0 = ATT + ENC + nt*128, kofs = ks*256;
    tc16_core<256>(sbuf,
                   g_hh + lr*DEC + kofs,
                   g_Whph + (size_t)(gn0+lr)*DEC + kofs,
                   g_Whph + (size_t)(gn0+lr+64)*DEC + kofs, acc);
    int r0=mr*16+(lane>>2), c0=(lane&3)*2;
    float* out = g_hppart + (size_t)ks*HPS;
    #pragma unroll
    for (int j=0;j<8;j++){
      int gn=gn0+nc*64+j*8+c0;
      out[(size_t)r0*HPN + gn]       = acc[j][0];
      out[(size_t)r0*HPN + gn+1]     = acc[j][1];
      out[(size_t)(r0+8)*HPN + gn]   = acc[j][2];
      out[(size_t)(r0+8)*HPN + gn+1] = acc[j][3];
    }
  }
}

// ph4: lstm — sums hWhh(2) + gates(8) partials + eg + biases; records history
__global__ void k_lstm(const float* __restrict__ b_ih, const float* __restrict__ b_hh, int t){
  int b = blockIdx.x;
  if (b >= g_bact[t]) return;
  int j = threadIdx.x;
  const float* eg  = g_eg + ((size_t)b*TSTEPS + t)*G4;
  const float* hp0 = g_hppart + (size_t)b*HPN + ATT + ENC;
  const float* hp1 = g_hppart + HPS + (size_t)b*HPN + ATT + ENC;
  float g[4];
  #pragma unroll
  for (int q=0;q<4;q++){
    int off = q*DEC + j;
    float v = eg[off] + b_ih[off] + b_hh[off] + hp0[off] + hp1[off];
    #pragma unroll
    for (int s=0;s<8;s++) v += g_gpart[(size_t)s*GS + (size_t)b*G4 + off];
    g[q] = v;
  }
  float cn = sigmoidf_(g[1])*g_c[b*DEC+j] + sigmoidf_(g[0])*tanhf(g[2]);
  float hn = sigmoidf_(g[3])*tanhf(cn);
  g_c[b*DEC+j]=cn;
  __half hh = __float2half_rn(hn);
  g_hh[b*DEC+j] = hh;
  g_hhist[((size_t)b*TSTEPS + t)*DEC + j] = hh;
}

// deferred batched fc: preds[b,t,:] = hhist[b*T+t] @ fc_W^T + fc_b. grid (157, 31)
__global__ void __launch_bounds__(256) k_fcall(const float* __restrict__ bias,
                                               float* __restrict__ preds){
  __shared__ __align__(16) __half2 sbuf[SBUF_H2];
  int m0 = blockIdx.y*64, gn0 = blockIdx.x*128;
  int tid=threadIdx.x, lane=tid&31, wp=tid>>5;
  int mr=wp>>1, nc=wp&1, lr=tid>>2;
  int wn0 = gn0 + lr;      if (wn0 >= V) wn0 = V-1;
  int wn1 = gn0 + lr + 64; if (wn1 >= V) wn1 = V-1;
  float acc[8][4]; ACC_INIT(acc)
  tc16_core<DEC>(sbuf,
                 g_hhist + (size_t)(m0+lr)*DEC,
                 g_fcWh + (size_t)wn0*DEC, g_fcWh + (size_t)wn1*DEC, acc);
  int r0 = m0 + mr*16 + (lane>>2);
  int r1 = r0 + 8;
  int c0 = (lane&3)*2;
  bool a0 = (r0 / TSTEPS) < g_bact[r0 % TSTEPS];
  bool a1 = (r1 / TSTEPS) < g_bact[r1 % TSTEPS];
  float* row0 = preds + (size_t)r0*V;
  float* row1 = preds + (size_t)r1*V;
  #pragma unroll
  for (int j=0;j<8;j++){
    int gn=gn0+nc*64+j*8+c0;
    if (gn < V){
      row0[gn] = a0 ? (acc[j][0]+bias[gn]) : 0.f;
      row1[gn] = a1 ? (acc[j][2]+bias[gn]) : 0.f;
    }
    if (gn+1 < V){
      row0[gn+1] = a0 ? (acc[j][1]+bias[gn+1]) : 0.f;
      row1[gn+1] = a1 ? (acc[j][3]+bias[gn+1]) : 0.f;
    }
  }
}

// ---------------- launch ----------------
extern "C" void kernel_launch(void* const* d_in, const int* in_sizes, int n_in,
                              void* d_out, int out_size){
  (void)in_sizes; (void)n_in; (void)out_size;
  const float* enc       = (const float*)d_in[0];
  const int*   caps      = (const int*)  d_in[1];
  const int*   caplen    = (const int*)  d_in[2];
  const float* emb_table = (const float*)d_in[3];
  const float* W_enc_att = (const float*)d_in[4];
  const float* b_enc_att = (const float*)d_in[5];
  const float* W_dec_att = (const float*)d_in[6];
  const float* b_dec_att = (const float*)d_in[7];
  const float* w_full    = (const float*)d_in[8];
  const float* b_full    = (const float*)d_in[9];
  const float* W_init_h  = (const float*)d_in[10];
  const float* b_init_h  = (const float*)d_in[11];
  const float* W_init_c  = (const float*)d_in[12];
  const float* b_init_c  = (const float*)d_in[13];
  const float* W_beta    = (const float*)d_in[14];
  const float* b_beta    = (const float*)d_in[15];
  const float* W_ih      = (const float*)d_in[16];
  const float* b_ih      = (const float*)d_in[17];
  const float* W_hh      = (const float*)d_in[18];
  const float* b_hh      = (const float*)d_in[19];
  const float* fc_W      = (const float*)d_in[20];
  const float* fc_b      = (const float*)d_in[21];

  float* preds  = (float*)d_out;                       // [B, T, V]
  float* alphas = preds + (size_t)B*TSTEPS*V;          // [B, T, P]

  k_bact<<<1, 32>>>(caplen);
  k_cvtmean<<<dim3(B, ENC/256), 256>>>(enc);
  k_cvtfcw<<<(int)(((size_t)V*DEC/4 + 255)/256), 256>>>(fc_W);
  k_cvtweah<<<(int)(((size_t)ATT*ENC/4 + 255)/256), 256>>>(W_enc_att);
  k_cvtembh<<<(int)(((size_t)V*EMB/4 + 255)/256), 256>>>(emb_table);
  k_cvthp<<<(int)(((size_t)HPN*DEC/4 + 255)/256), 256>>>(W_dec_att, W_beta, W_hh);
  k_cvtwih<<<(int)(((size_t)G4*XDIM/4 + 255)/256), 256>>>(W_ih);
  k_init<<<dim3(32,1,4), 256>>>(W_init_h, W_init_c);
  k_init_red<<<64, 256>>>(b_init_h, b_init_c);
  k_att1<<<dim3(ATT/128, (B*PP)/64), 256>>>(b_enc_att);
  k_embgate<<<dim3(G4/128, NH/64), 256>>>(caps);

  for (int t=0; t<TSTEPS; t++){
    k_ph1<<<40, 256>>>(t);
    k_ph2<<<B, 512>>>(b_dec_att, w_full, b_full, b_beta, alphas, t);
    k_ph3<<<160, 256>>>(t);
    k_lstm<<<B, DEC>>>(b_ih, b_hh, t);
  }
  k_fcall<<<dim3((V+127)/128, NH/64), 256>>>(fc_b, preds);
}

// round 13
// speedup vs baseline: 1.0949x; 1.0949x over previous
#include <cuda_runtime.h>
#include <cuda_fp16.h>
#include <cstdint>

#define B      64
#define PP     196
#define ENC    2048
#define LCAP   32
#define V      20000
#define ATT    512
#define EMB    512
#define DEC    512
#define TSTEPS 31
#define XDIM   (EMB+ENC)   /* 2560 */
#define G4     (4*DEC)     /* 2048 */
#define NH     (B*TSTEPS)  /* 1984 */
#define HPN    (ATT+ENC+G4) /* 4608 */
#define HPS    ((size_t)B*HPN)
#define GS     ((size_t)B*G4)

// ---------------- device scratch ----------------
__device__ __half g_att1h[(size_t)B*PP*ATT];
__device__ __half g_ench[(size_t)B*PP*ENC];
__device__ __half g_fcWh[(size_t)V*DEC];
__device__ __half g_Whph[(size_t)HPN*DEC];      // [Wda;Wbeta;Whh] fp16
__device__ __half g_Wihh[(size_t)G4*ENC];       // W_ih[:,512:] fp16
__device__ __half g_Wihe[(size_t)G4*EMB];       // W_ih[:,:512] fp16
__device__ __half g_Weah[(size_t)ATT*ENC];      // W_enc_att fp16
__device__ __half g_embh[(size_t)V*EMB];        // emb_table fp16
__device__ __half g_hh[B*DEC];                  // h state fp16
__device__ __half g_hhist[(size_t)NH*DEC];      // h history (zero-init)
__device__ __half g_xeh[B*ENC];                 // gate*awe fp16
__device__ float  g_mean[B*ENC];
__device__ float  g_c[B*DEC];                   // c state fp32 exact
__device__ float  g_hppart[2*HPS];              // hproj split-K partials
__device__ float  g_gpart[8*GS];                // gates split-K partials
__device__ float  g_eg[(size_t)NH*G4];
__device__ float  g_ipart[4*64*1024];
__device__ int    g_bact[TSTEPS];

__device__ __forceinline__ float sigmoidf_(float x){ return 1.0f/(1.0f+expf(-x)); }
__device__ __forceinline__ void mma_f16(float* d, uint32_t a0, uint32_t a1, uint32_t a2, uint32_t a3,
                                        uint32_t b0, uint32_t b1){
  asm volatile("mma.sync.aligned.m16n8k16.row.col.f32.f16.f16.f32 "
    "{%0,%1,%2,%3},{%4,%5,%6,%7},{%8,%9},{%0,%1,%2,%3};"
    : "+f"(d[0]),"+f"(d[1]),"+f"(d[2]),"+f"(d[3])
    : "r"(a0),"r"(a1),"r"(a2),"r"(a3),"r"(b0),"r"(b1));
}

// ---------------- one-time kernels ----------------
__global__ void k_bact(const int* __restrict__ caplen){
  int t = threadIdx.x;
  if (t < TSTEPS){
    int c = 0;
    for (int b=0;b<B;b++) c += ((caplen[b]-1) > t) ? 1 : 0;
    g_bact[t] = c;
  }
}

__global__ void k_cvtmean(const float* __restrict__ enc){
  int b = blockIdx.x;
  int e = blockIdx.y*256 + threadIdx.x;
  const float* p0 = enc + (size_t)b*PP*ENC + e;
  __half* h0 = g_ench + (size_t)b*PP*ENC + e;
  float s = 0.f;
  #pragma unroll 4
  for (int p=0;p<PP;p++){
    float v = p0[(size_t)p*ENC];
    s += v;
    h0[(size_t)p*ENC] = __float2half_rn(v);
  }
  g_mean[b*ENC + e] = s * (1.0f/PP);
}

__global__ void k_cvtfcw(const float* __restrict__ W){
  size_t i = (size_t)blockIdx.x*blockDim.x + threadIdx.x;
  const size_t n4 = (size_t)V*DEC/4;
  if (i >= n4) return;
  float4 v = ((const float4*)W)[i];
  __half2* o = (__half2*)g_fcWh;
  o[i*2]   = __floats2half2_rn(v.x, v.y);
  o[i*2+1] = __floats2half2_rn(v.z, v.w);
}

__global__ void k_cvtweah(const float* __restrict__ W){
  size_t i = (size_t)blockIdx.x*blockDim.x + threadIdx.x;
  const size_t n4 = (size_t)ATT*ENC/4;
  if (i >= n4) return;
  float4 v = ((const float4*)W)[i];
  __half2* o = (__half2*)g_Weah;
  o[i*2]   = __floats2half2_rn(v.x, v.y);
  o[i*2+1] = __floats2half2_rn(v.z, v.w);
}

__global__ void k_cvtembh(const float* __restrict__ E){
  size_t i = (size_t)blockIdx.x*blockDim.x + threadIdx.x;
  const size_t n4 = (size_t)V*EMB/4;
  if (i >= n4) return;
  float4 v = ((const float4*)E)[i];
  __half2* o = (__half2*)g_embh;
  o[i*2]   = __floats2half2_rn(v.x, v.y);
  o[i*2+1] = __floats2half2_rn(v.z, v.w);
}

__global__ void k_cvthp(const float* __restrict__ Wda, const float* __restrict__ Wbeta,
                        const float* __restrict__ Whh){
  size_t i = (size_t)blockIdx.x*blockDim.x + threadIdx.x;
  const size_t n4 = (size_t)HPN*DEC/4;
  if (i >= n4) return;
  size_t el = i*4;
  int row = (int)(el / DEC), col = (int)(el % DEC);
  const float* src;
  if (row < ATT)          src = Wda   + (size_t)row*DEC;
  else if (row < ATT+ENC) src = Wbeta + (size_t)(row-ATT)*DEC;
  else                    src = Whh   + (size_t)(row-ATT-ENC)*DEC;
  float4 v = *(const float4*)(src + col);
  __half2* o = (__half2*)(g_Whph + el);
  o[0] = __floats2half2_rn(v.x, v.y);
  o[1] = __floats2half2_rn(v.z, v.w);
}

__global__ void k_cvtwih(const float* __restrict__ Wih){
  size_t i = (size_t)blockIdx.x*blockDim.x + threadIdx.x;
  const size_t n4 = (size_t)G4*XDIM/4;
  if (i >= n4) return;
  size_t el = i*4;
  int row = (int)(el / XDIM), col = (int)(el % XDIM);
  float4 v = *(const float4*)(Wih + el);
  __half2 h0 = __floats2half2_rn(v.x, v.y);
  __half2 h1 = __floats2half2_rn(v.z, v.w);
  if (col < EMB){
    __half2* o = (__half2*)(g_Wihe + (size_t)row*EMB + col);
    o[0]=h0; o[1]=h1;
  } else {
    __half2* o = (__half2*)(g_Wihh + (size_t)row*ENC + (col-EMB));
    o[0]=h0; o[1]=h1;
  }
}

__global__ void k_init(const float* __restrict__ Wh, const float* __restrict__ Wc){
  __shared__ float sA[32][68];
  __shared__ float sW[32][34];
  int tid = threadIdx.x, tx = tid & 15, ty = tid >> 4;
  int gn0 = blockIdx.x * 32;
  int ks  = blockIdx.z;
  const float* Wp = (gn0 < DEC) ? (Wh + (size_t)gn0*ENC) : (Wc + (size_t)(gn0-DEC)*ENC);
  float acc[4][2] = {};
  for (int k0=ks*512; k0<ks*512+512; k0+=32){
    #pragma unroll
    for (int i=0;i<2;i++){
      int lin = tid + i*256, row = lin >> 3, kq = lin & 7;
      float4 v = *(const float4*)(g_mean + row*ENC + k0 + kq*4);
      sA[kq*4+0][row]=v.x; sA[kq*4+1][row]=v.y; sA[kq*4+2][row]=v.z; sA[kq*4+3][row]=v.w;
    }
    {
      int n = tid >> 3, kq = tid & 7;
      float4 v = *(const float4*)(Wp + (size_t)n*ENC + k0 + kq*4);
      sW[kq*4+0][n]=v.x; sW[kq*4+1][n]=v.y; sW[kq*4+2][n]=v.z; sW[kq*4+3][n]=v.w;
    }
    __syncthreads();
    #pragma unroll
    for (int k=0;k<32;k++){
      float4 a = *(const float4*)&sA[k][ty*4];
      float2 w = *(const float2*)&sW[k][tx*2];
      acc[0][0]+=a.x*w.x; acc[0][1]+=a.x*w.y;
      acc[1][0]+=a.y*w.x; acc[1][1]+=a.y*w.y;
      acc[2][0]+=a.z*w.x; acc[2][1]+=a.z*w.y;
      acc[3][0]+=a.w*w.x; acc[3][1]+=a.w*w.y;
    }
    __syncthreads();
  }
  #pragma unroll
  for (int i=0;i<4;i++){
    int m = ty*4+i;
    #pragma unroll
    for (int j=0;j<2;j++)
      g_ipart[(size_t)ks*64*1024 + m*1024 + gn0 + tx*2 + j] = acc[i][j];
  }
}

__global__ void k_init_red(const float* __restrict__ bh, const float* __restrict__ bc){
  int m = blockIdx.x;
  for (int c=threadIdx.x; c<1024; c+=256){
    float v = g_ipart[m*1024+c] + g_ipart[64*1024 + m*1024+c]
            + g_ipart[2*64*1024 + m*1024+c] + g_ipart[3*64*1024 + m*1024+c];
    if (c < DEC) g_hh[m*DEC + c]      = __float2half_rn(v + bh[c]);
    else         g_c[m*DEC + (c-DEC)] = v + bc[c-DEC];
  }
}

// ---------------- fp16 mma core, double-buffered (M=64, BN=128) ----------------
template<int KLEN>
__device__ __forceinline__ void tc16_core(__half2* sbuf,
    const __half* Ap, const __half* Wp0, const __half* Wp1, float acc[8][4]){
  __half2* sA0 = sbuf;
  __half2* sW0 = sbuf + 2*64*20;
  const int AS = 64*20, WS = 128*20;
  int tid=threadIdx.x, lane=tid&31, wp=tid>>5;
  int mr=wp>>1, nc=wp&1;
  int lr=tid>>2, kq8=(tid&3)*8;
  int r = mr*16 + (lane>>2);
  int cq = lane&3;
  uint4 a  = *(const uint4*)(Ap + kq8);
  uint4 w0 = *(const uint4*)(Wp0 + kq8);
  uint4 w1 = *(const uint4*)(Wp1 + kq8);
  *(uint4*)(sA0 + lr*20 + kq8/2)      = a;
  *(uint4*)(sW0 + lr*20 + kq8/2)      = w0;
  *(uint4*)(sW0 + (lr+64)*20 + kq8/2) = w1;
  __syncthreads();
  for (int k0=0;k0<KLEN;k0+=32){
    int cur = (k0>>5)&1;
    __half2* cA = sA0 + cur*AS;
    __half2* cW = sW0 + cur*WS;
    if (k0+32<KLEN){
      a  = *(const uint4*)(Ap + k0+32 + kq8);
      w0 = *(const uint4*)(Wp0 + k0+32 + kq8);
      w1 = *(const uint4*)(Wp1 + k0+32 + kq8);
      __half2* nA = sA0 + (cur^1)*AS;
      __half2* nW = sW0 + (cur^1)*WS;
      *(uint4*)(nA + lr*20 + kq8/2)      = a;
      *(uint4*)(nW + lr*20 + kq8/2)      = w0;
      *(uint4*)(nW + (lr+64)*20 + kq8/2) = w1;
    }
    #pragma unroll
    for (int kk=0;kk<2;kk++){
      int o = kk*8 + cq;
      uint32_t a0=*(uint32_t*)(cA + r*20 + o);
      uint32_t a1=*(uint32_t*)(cA + (r+8)*20 + o);
      uint32_t a2=*(uint32_t*)(cA + r*20 + o+4);
      uint32_t a3=*(uint32_t*)(cA + (r+8)*20 + o+4);
      #pragma unroll
      for (int j=0;j<8;j++){
        int n = nc*64 + j*8 + (lane>>2);
        uint32_t b0=*(uint32_t*)(cW + n*20 + o);
        uint32_t b1=*(uint32_t*)(cW + n*20 + o+4);
        mma_f16(acc[j], a0, a1, a2, a3, b0, b1);
      }
    }
    __syncthreads();
  }
}
#define SBUF_H2 (2*(64*20 + 128*20))
#define ACC_INIT(acc) { _Pragma("unroll") for (int j=0;j<8;j++){ acc[j][0]=acc[j][1]=acc[j][2]=acc[j][3]=0.f; } }

// one-time: att1 = ench @ W_enc_att^T + bias (fp16 mma). grid (4, 196)
__global__ void __launch_bounds__(256) k_att1(const float* __restrict__ bias){
  __shared__ __align__(16) __half2 sbuf[SBUF_H2];
  int m0 = blockIdx.y*64, gn0 = blockIdx.x*128;
  int tid=threadIdx.x, lane=tid&31, wp=tid>>5;
  int mr=wp>>1, nc=wp&1, lr=tid>>2;
  float acc[8][4]; ACC_INIT(acc)
  tc16_core<ENC>(sbuf,
                 g_ench + (size_t)(m0+lr)*ENC,
                 g_Weah + (size_t)(gn0+lr)*ENC,
                 g_Weah + (size_t)(gn0+lr+64)*ENC, acc);
  int r0=m0+mr*16+(lane>>2), c0=(lane&3)*2;
  #pragma unroll
  for (int j=0;j<8;j++){
    int gn=gn0+nc*64+j*8+c0;
    *(__half2*)(g_att1h + (size_t)r0*ATT + gn)     = __floats2half2_rn(acc[j][0]+bias[gn], acc[j][1]+bias[gn+1]);
    *(__half2*)(g_att1h + (size_t)(r0+8)*ATT + gn) = __floats2half2_rn(acc[j][2]+bias[gn], acc[j][3]+bias[gn+1]);
  }
}

// one-time: g_eg = emb[tok] @ W_ih[:, :512]^T (fp16 mma). grid (16, 31)
__global__ void __launch_bounds__(256) k_embgate(const int* __restrict__ caps){
  __shared__ __align__(16) __half2 sbuf[SBUF_H2];
  int m0 = blockIdx.y*64, gn0 = blockIdx.x*128;
  int tid=threadIdx.x, lane=tid&31, wp=tid>>5;
  int mr=wp>>1, nc=wp&1, lr=tid>>2;
  int gr = m0 + lr;
  int tok = caps[(gr/TSTEPS)*LCAP + (gr%TSTEPS)];
  float acc[8][4]; ACC_INIT(acc)
  tc16_core<EMB>(sbuf,
                 g_embh + (size_t)tok*EMB,
                 g_Wihe + (size_t)(gn0+lr)*EMB,
                 g_Wihe + (size_t)(gn0+lr+64)*EMB, acc);
  int r0=m0+mr*16+(lane>>2), c0=(lane&3)*2;
  #pragma unroll
  for (int j=0;j<8;j++){
    int gn=gn0+nc*64+j*8+c0;
    g_eg[(size_t)r0*G4 + gn]       = acc[j][0];
    g_eg[(size_t)r0*G4 + gn+1]     = acc[j][1];
    g_eg[(size_t)(r0+8)*G4 + gn]   = acc[j][2];
    g_eg[(size_t)(r0+8)*G4 + gn+1] = acc[j][3];
  }
}

// ---------------- per-step kernels ----------------
// ph1: hproj full [Wda;Wbeta;Whh] split-K2: 72 tiles; tile = ks*36 + nt
__global__ void __launch_bounds__(256) k_ph1(int t){
  (void)t;
  __shared__ __align__(16) __half2 sbuf[SBUF_H2];
  int tile = blockIdx.x;
  int nt = tile % 36, ks = tile / 36;
  int gn0 = nt*128, kofs = ks*256;
  int tid=threadIdx.x, lane=tid&31, wp=tid>>5;
  int mr=wp>>1, nc=wp&1, lr=tid>>2;
  float acc[8][4]; ACC_INIT(acc)
  tc16_core<256>(sbuf,
                 g_hh + lr*DEC + kofs,
                 g_Whph + (size_t)(gn0+lr)*DEC + kofs,
                 g_Whph + (size_t)(gn0+lr+64)*DEC + kofs, acc);
  int r0=mr*16+(lane>>2), c0=(lane&3)*2;
  float* out = g_hppart + (size_t)ks*HPS;
  #pragma unroll
  for (int j=0;j<8;j++){
    int gn=gn0+nc*64+j*8+c0;
    out[(size_t)r0*HPN + gn]       = acc[j][0];
    out[(size_t)r0*HPN + gn+1]     = acc[j][1];
    out[(size_t)(r0+8)*HPN + gn]   = acc[j][2];
    out[(size_t)(r0+8)*HPN + gn+1] = acc[j][3];
  }
}

// ph2: alpha+awe (tile = b*2 + half), 256 threads
__global__ void __launch_bounds__(256) k_ph2(
    const float* __restrict__ b_dec_att, const float* __restrict__ w_full,
    const float* __restrict__ b_full, const float* __restrict__ b_beta,
    float* __restrict__ alphas, int t){
  int tile = blockIdx.x;
  int b = tile >> 1, half = tile & 1;
  int tid = threadIdx.x;
  int nact = g_bact[t];
  if (b >= nact){
    if (half == 0)
      for (int p=tid;p<PP;p+=256) alphas[(size_t)b*TSTEPS*PP + (size_t)t*PP + p] = 0.f;
    return;
  }
  __shared__ float s_a2[ATT];
  __shared__ float s_wf[ATT];
  __shared__ float s_e[200];
  __shared__ float s_red[8];
  const float* hp0 = g_hppart + (size_t)b*HPN;
  const float* hp1 = g_hppart + HPS + (size_t)b*HPN;
  for (int a=tid;a<ATT;a+=256){
    s_a2[a] = hp0[a] + hp1[a] + b_dec_att[a];
    s_wf[a] = w_full[a];
  }
  __syncthreads();
  int warp = tid>>5, lane = tid&31;
  float bf = b_full[0];
  for (int p=warp; p<PP; p+=8){
    const __half2* r = (const __half2*)(g_att1h + (size_t)(b*PP+p)*ATT);
    float s=0.f;
    #pragma unroll
    for (int i=0;i<8;i++){
      int a2i = lane + i*32;
      float2 f = __half22float2(r[a2i]);
      int a = a2i*2;
      s += fmaxf(f.x + s_a2[a],0.f)*s_wf[a] + fmaxf(f.y + s_a2[a+1],0.f)*s_wf[a+1];
    }
    #pragma unroll
    for (int o=16;o;o>>=1) s += __shfl_xor_sync(0xffffffffu,s,o);
    if (lane==0) s_e[p] = s + bf;
  }
  __syncthreads();
  float m = (tid < PP) ? s_e[tid] : -1e30f;
  #pragma unroll
  for (int o=16;o;o>>=1) m = fmaxf(m,__shfl_xor_sync(0xffffffffu,m,o));
  if (lane==0) s_red[warp]=m;
  __syncthreads();
  float mx = s_red[0];
  #pragma unroll
  for (int i=1;i<8;i++) mx = fmaxf(mx, s_red[i]);
  __syncthreads();
  float sum = 0.f;
  if (tid < PP){ float ex = expf(s_e[tid]-mx); s_e[tid]=ex; sum=ex; }
  #pragma unroll
  for (int o=16;o;o>>=1) sum += __shfl_xor_sync(0xffffffffu,sum,o);
  if (lane==0) s_red[warp]=sum;
  __syncthreads();
  float tot = 0.f;
  #pragma unroll
  for (int i=0;i<8;i++) tot += s_red[i];
  float inv = 1.0f/tot;
  if (tid < PP){
    float al = s_e[tid]*inv;
    s_e[tid] = al;
    if (half == 0) alphas[(size_t)b*TSTEPS*PP + (size_t)t*PP + tid] = al;
  }
  __syncthreads();
  const __half2* eb = (const __half2*)g_ench + (size_t)b*PP*(ENC/2);
  int c0 = half*512 + tid;
  int c1 = c0 + 256;
  float ax=0.f, ay=0.f, cx=0.f, cy=0.f;
  #pragma unroll 2
  for (int p=0;p<PP;p++){
    float al = s_e[p];
    float2 f0 = __half22float2(eb[(size_t)p*(ENC/2) + c0]);
    float2 f1 = __half22float2(eb[(size_t)p*(ENC/2) + c1]);
    ax += al*f0.x; ay += al*f0.y;
    cx += al*f1.x; cy += al*f1.y;
  }
  int e = c0*2;
  float g0 = sigmoidf_(hp0[ATT+e]   + hp1[ATT+e]   + b_beta[e]);
  float g1 = sigmoidf_(hp0[ATT+e+1] + hp1[ATT+e+1] + b_beta[e+1]);
  *(__half2*)(g_xeh + (size_t)b*ENC + e) = __floats2half2_rn(g0*ax, g1*ay);
  int e2 = c1*2;
  float g2 = sigmoidf_(hp0[ATT+e2]   + hp1[ATT+e2]   + b_beta[e2]);
  float g3 = sigmoidf_(hp0[ATT+e2+1] + hp1[ATT+e2+1] + b_beta[e2+1]);
  *(__half2*)(g_xeh + (size_t)b*ENC + e2) = __floats2half2_rn(g2*cx, g3*cy);
}

// ph3: gates split-K8: 128 tiles; tile = ks*16 + nt
__global__ void __launch_bounds__(256) k_ph3(int t){
  (void)t;
  __shared__ __align__(16) __half2 sbuf[SBUF_H2];
  int tile = blockIdx.x;
  int nt = tile & 15, ks = tile >> 4;
  int gn0 = nt*128, kofs = ks*256;
  int tid=threadIdx.x, lane=tid&31, wp=tid>>5;
  int mr=wp>>1, nc=wp&1, lr=tid>>2;
  float acc[8][4]; ACC_INIT(acc)
  tc16_core<256>(sbuf,
                 g_xeh + (size_t)lr*ENC + kofs,
                 g_Wihh + (size_t)(gn0+lr)*ENC + kofs,
                 g_Wihh + (size_t)(gn0+lr+64)*ENC + kofs, acc);
  int r0=mr*16+(lane>>2), c0=(lane&3)*2;
  float* out = g_gpart + (size_t)ks*GS;
  #pragma unroll
  for (int j=0;j<8;j++){
    int gn=gn0+nc*64+j*8+c0;
    out[(size_t)r0*G4 + gn]       = acc[j][0];
    out[(size_t)r0*G4 + gn+1]     = acc[j][1];
    out[(size_t)(r0+8)*G4 + gn]   = acc[j][2];
    out[(size_t)(r0+8)*G4 + gn+1] = acc[j][3];
  }
}

// ph4: lstm — sums hproj(2) + gates(8) partials + eg + biases; records history
__global__ void k_lstm(const float* __restrict__ b_ih, const float* __restrict__ b_hh, int t){
  int b = blockIdx.x;
  if (b >= g_bact[t]) return;
  int j = threadIdx.x;
  const float* eg  = g_eg + ((size_t)b*TSTEPS + t)*G4;
  const float* hp0 = g_hppart + (size_t)b*HPN + ATT + ENC;
  const float* hp1 = g_hppart + HPS + (size_t)b*HPN + ATT + ENC;
  float g[4];
  #pragma unroll
  for (int q=0;q<4;q++){
    int off = q*DEC + j;
    float v = eg[off] + b_ih[off] + b_hh[off] + hp0[off] + hp1[off];
    #pragma unroll
    for (int s=0;s<8;s++) v += g_gpart[(size_t)s*GS + (size_t)b*G4 + off];
    g[q] = v;
  }
  float cn = sigmoidf_(g[1])*g_c[b*DEC+j] + sigmoidf_(g[0])*tanhf(g[2]);
  float hn = sigmoidf_(g[3])*tanhf(cn);
  g_c[b*DEC+j]=cn;
  __half hh = __float2half_rn(hn);
  g_hh[b*DEC+j] = hh;
  g_hhist[((size_t)b*TSTEPS + t)*DEC + j] = hh;
}

// deferred batched fc: preds[b,t,:] = hhist[b*T+t] @ fc_W^T + fc_b. grid (157, 31)
__global__ void __launch_bounds__(256) k_fcall(const float* __restrict__ bias,
                                               float* __restrict__ preds){
  __shared__ __align__(16) __half2 sbuf[SBUF_H2];
  int m0 = blockIdx.y*64, gn0 = blockIdx.x*128;
  int tid=threadIdx.x, lane=tid&31, wp=tid>>5;
  int mr=wp>>1, nc=wp&1, lr=tid>>2;
  int wn0 = gn0 + lr;      if (wn0 >= V) wn0 = V-1;
  int wn1 = gn0 + lr + 64; if (wn1 >= V) wn1 = V-1;
  float acc[8][4]; ACC_INIT(acc)
  tc16_core<DEC>(sbuf,
                 g_hhist + (size_t)(m0+lr)*DEC,
                 g_fcWh + (size_t)wn0*DEC, g_fcWh + (size_t)wn1*DEC, acc);
  int r0 = m0 + mr*16 + (lane>>2);
  int r1 = r0 + 8;
  int c0 = (lane&3)*2;
  bool a0 = (r0 / TSTEPS) < g_bact[r0 % TSTEPS];
  bool a1 = (r1 / TSTEPS) < g_bact[r1 % TSTEPS];
  float* row0 = preds + (size_t)r0*V;
  float* row1 = preds + (size_t)r1*V;
  #pragma unroll
  for (int j=0;j<8;j++){
    int gn=gn0+nc*64+j*8+c0;
    if (gn < V){
      row0[gn] = a0 ? (acc[j][0]+bias[gn]) : 0.f;
      row1[gn] = a1 ? (acc[j][2]+bias[gn]) : 0.f;
    }
    if (gn+1 < V){
      row0[gn+1] = a0 ? (acc[j][1]+bias[gn+1]) : 0.f;
      row1[gn+1] = a1 ? (acc[j][3]+bias[gn+1]) : 0.f;
    }
  }
}

// ---------------- launch ----------------
extern "C" void kernel_launch(void* const* d_in, const int* in_sizes, int n_in,
                              void* d_out, int out_size){
  (void)in_sizes; (void)n_in; (void)out_size;
  const float* enc       = (const float*)d_in[0];
  const int*   caps      = (const int*)  d_in[1];
  const int*   caplen    = (const int*)  d_in[2];
  const float* emb_table = (const float*)d_in[3];
  const float* W_enc_att = (const float*)d_in[4];
  const float* b_enc_att = (const float*)d_in[5];
  const float* W_dec_att = (const float*)d_in[6];
  const float* b_dec_att = (const float*)d_in[7];
  const float* w_full    = (const float*)d_in[8];
  const float* b_full    = (const float*)d_in[9];
  const float* W_init_h  = (const float*)d_in[10];
  const float* b_init_h  = (const float*)d_in[11];
  const float* W_init_c  = (const float*)d_in[12];
  const float* b_init_c  = (const float*)d_in[13];
  const float* W_beta    = (const float*)d_in[14];
  const float* b_beta    = (const float*)d_in[15];
  const float* W_ih      = (const float*)d_in[16];
  const float* b_ih      = (const float*)d_in[17];
  const float* W_hh      = (const float*)d_in[18];
  const float* b_hh      = (const float*)d_in[19];
  const float* fc_W      = (const float*)d_in[20];
  const float* fc_b      = (const float*)d_in[21];

  float* preds  = (float*)d_out;                       // [B, T, V]
  float* alphas = preds + (size_t)B*TSTEPS*V;          // [B, T, P]

  k_bact<<<1, 32>>>(caplen);
  k_cvtmean<<<dim3(B, ENC/256), 256>>>(enc);
  k_cvtfcw<<<(int)(((size_t)V*DEC/4 + 255)/256), 256>>>(fc_W);
  k_cvtweah<<<(int)(((size_t)ATT*ENC/4 + 255)/256), 256>>>(W_enc_att);
  k_cvtembh<<<(int)(((size_t)V*EMB/4 + 255)/256), 256>>>(emb_table);
  k_cvthp<<<(int)(((size_t)HPN*DEC/4 + 255)/256), 256>>>(W_dec_att, W_beta, W_hh);
  k_cvtwih<<<(int)(((size_t)G4*XDIM/4 + 255)/256), 256>>>(W_ih);
  k_init<<<dim3(32,1,4), 256>>>(W_init_h, W_init_c);
  k_init_red<<<64, 256>>>(b_init_h, b_init_c);
  k_att1<<<dim3(ATT/128, (B*PP)/64), 256>>>(b_enc_att);
  k_embgate<<<dim3(G4/128, NH/64), 256>>>(caps);

  for (int t=0; t<TSTEPS; t++){
    k_ph1<<<72, 256>>>(t);
    k_ph2<<<2*B, 256>>>(b_dec_att, w_full, b_full, b_beta, alphas, t);
    k_ph3<<<128, 256>>>(t);
    k_lstm<<<B, DEC>>>(b_ih, b_hh, t);
  }
  k_fcall<<<dim3((V+127)/128, NH/64), 256>>>(fc_b, preds);
}

// round 14
// speedup vs baseline: 1.1133x; 1.0169x over previous
#include <cuda_runtime.h>
#include <cuda_fp16.h>
#include <cstdint>

#define B      64
#define PP     196
#define ENC    2048
#define LCAP   32
#define V      20000
#define ATT    512
#define EMB    512
#define DEC    512
#define TSTEPS 31
#define XDIM   (EMB+ENC)   /* 2560 */
#define G4     (4*DEC)     /* 2048 */
#define NH     (B*TSTEPS)  /* 1984 */
#define HPN    (ATT+ENC+G4) /* 4608 */
#define HPS    ((size_t)B*HPN)
#define GS     ((size_t)B*G4)

// ---------------- device scratch ----------------
__device__ __half g_att1h[(size_t)B*PP*ATT];
__device__ __half g_ench[(size_t)B*PP*ENC];
__device__ __half g_fcWh[(size_t)V*DEC];
__device__ __half g_Whph[(size_t)HPN*DEC];
__device__ __half g_Wihh[(size_t)G4*ENC];
__device__ __half g_Wihe[(size_t)G4*EMB];
__device__ __half g_Weah[(size_t)ATT*ENC];
__device__ __half g_embh[(size_t)V*EMB];
__device__ __half g_hh[B*DEC];
__device__ __half g_hhist[(size_t)NH*DEC];
__device__ __half g_xeh[B*ENC];
__device__ float  g_mean[B*ENC];
__device__ float  g_c[B*DEC];
__device__ float  g_hppart[2*HPS];
__device__ float  g_gpart[8*GS];
__device__ float  g_eg[(size_t)NH*G4];
__device__ float  g_ipart[4*64*1024];
__device__ int    g_bact[TSTEPS];
__device__ int    g_cnt3[TSTEPS];   // ph3 arrival counters (reset by ph1 of same t)

__device__ __forceinline__ float sigmoidf_(float x){ return 1.0f/(1.0f+expf(-x)); }
__device__ __forceinline__ void mma_f16(float* d, uint32_t a0, uint32_t a1, uint32_t a2, uint32_t a3,
                                        uint32_t b0, uint32_t b1){
  asm volatile("mma.sync.aligned.m16n8k16.row.col.f32.f16.f16.f32 "
    "{%0,%1,%2,%3},{%4,%5,%6,%7},{%8,%9},{%0,%1,%2,%3};"
    : "+f"(d[0]),"+f"(d[1]),"+f"(d[2]),"+f"(d[3])
    : "r"(a0),"r"(a1),"r"(a2),"r"(a3),"r"(b0),"r"(b1));
}

// ---------------- one-time kernels ----------------
__global__ void k_bact(const int* __restrict__ caplen){
  int t = threadIdx.x;
  if (t < TSTEPS){
    int c = 0;
    for (int b=0;b<B;b++) c += ((caplen[b]-1) > t) ? 1 : 0;
    g_bact[t] = c;
  }
}

__global__ void k_cvtmean(const float* __restrict__ enc){
  int b = blockIdx.x;
  int e = blockIdx.y*256 + threadIdx.x;
  const float* p0 = enc + (size_t)b*PP*ENC + e;
  __half* h0 = g_ench + (size_t)b*PP*ENC + e;
  float s = 0.f;
  #pragma unroll 4
  for (int p=0;p<PP;p++){
    float v = p0[(size_t)p*ENC];
    s += v;
    h0[(size_t)p*ENC] = __float2half_rn(v);
  }
  g_mean[b*ENC + e] = s * (1.0f/PP);
}

// merged fp32->fp16 converter for all weight tensors (segmented, one launch)
#define N4_FCW  ((size_t)V*DEC/4)
#define N4_WEAH ((size_t)ATT*ENC/4)
#define N4_EMBH ((size_t)V*EMB/4)
#define N4_HP   ((size_t)HPN*DEC/4)
#define N4_WIH  ((size_t)G4*XDIM/4)
#define N4_ALL  (N4_FCW + N4_WEAH + N4_EMBH + N4_HP + N4_WIH)
__global__ void k_cvtall(const float* __restrict__ fcW, const float* __restrict__ weah,
                         const float* __restrict__ embt, const float* __restrict__ Wda,
                         const float* __restrict__ Wbeta, const float* __restrict__ Whh,
                         const float* __restrict__ Wih){
  size_t i = (size_t)blockIdx.x*blockDim.x + threadIdx.x;
  if (i >= N4_ALL) return;
  float4 v;
  __half2* o;
  if (i < N4_FCW){
    v = ((const float4*)fcW)[i];
    o = (__half2*)(g_fcWh) + i*2;
  } else if (i < N4_FCW + N4_WEAH){
    size_t k = i - N4_FCW;
    v = ((const float4*)weah)[k];
    o = (__half2*)(g_Weah) + k*2;
  } else if (i < N4_FCW + N4_WEAH + N4_EMBH){
    size_t k = i - N4_FCW - N4_WEAH;
    v = ((const float4*)embt)[k];
    o = (__half2*)(g_embh) + k*2;
  } else if (i < N4_FCW + N4_WEAH + N4_EMBH + N4_HP){
    size_t k = i - N4_FCW - N4_WEAH - N4_EMBH;
    size_t el = k*4;
    int row = (int)(el / DEC), col = (int)(el % DEC);
    const float* src;
    if (row < ATT)          src = Wda   + (size_t)row*DEC;
    else if (row < ATT+ENC) src = Wbeta + (size_t)(row-ATT)*DEC;
    else                    src = Whh   + (size_t)(row-ATT-ENC)*DEC;
    v = *(const float4*)(src + col);
    o = (__half2*)(g_Whph + el);
  } else {
    size_t k = i - N4_FCW - N4_WEAH - N4_EMBH - N4_HP;
    size_t el = k*4;
    int row = (int)(el / XDIM), col = (int)(el % XDIM);
    v = *(const float4*)(Wih + el);
    if (col < EMB) o = (__half2*)(g_Wihe + (size_t)row*EMB + col);
    else           o = (__half2*)(g_Wihh + (size_t)row*ENC + (col-EMB));
  }
  o[0] = __floats2half2_rn(v.x, v.y);
  o[1] = __floats2half2_rn(v.z, v.w);
}

__global__ void k_init(const float* __restrict__ Wh, const float* __restrict__ Wc){
  __shared__ float sA[32][68];
  __shared__ float sW[32][34];
  int tid = threadIdx.x, tx = tid & 15, ty = tid >> 4;
  int gn0 = blockIdx.x * 32;
  int ks  = blockIdx.z;
  const float* Wp = (gn0 < DEC) ? (Wh + (size_t)gn0*ENC) : (Wc + (size_t)(gn0-DEC)*ENC);
  float acc[4][2] = {};
  for (int k0=ks*512; k0<ks*512+512; k0+=32){
    #pragma unroll
    for (int i=0;i<2;i++){
      int lin = tid + i*256, row = lin >> 3, kq = lin & 7;
      float4 v = *(const float4*)(g_mean + row*ENC + k0 + kq*4);
      sA[kq*4+0][row]=v.x; sA[kq*4+1][row]=v.y; sA[kq*4+2][row]=v.z; sA[kq*4+3][row]=v.w;
    }
    {
      int n = tid >> 3, kq = tid & 7;
      float4 v = *(const float4*)(Wp + (size_t)n*ENC + k0 + kq*4);
      sW[kq*4+0][n]=v.x; sW[kq*4+1][n]=v.y; sW[kq*4+2][n]=v.z; sW[kq*4+3][n]=v.w;
    }
    __syncthreads();
    #pragma unroll
    for (int k=0;k<32;k++){
      float4 a = *(const float4*)&sA[k][ty*4];
      float2 w = *(const float2*)&sW[k][tx*2];
      acc[0][0]+=a.x*w.x; acc[0][1]+=a.x*w.y;
      acc[1][0]+=a.y*w.x; acc[1][1]+=a.y*w.y;
      acc[2][0]+=a.z*w.x; acc[2][1]+=a.z*w.y;
      acc[3][0]+=a.w*w.x; acc[3][1]+=a.w*w.y;
    }
    __syncthreads();
  }
  #pragma unroll
  for (int i=0;i<4;i++){
    int m = ty*4+i;
    #pragma unroll
    for (int j=0;j<2;j++)
      g_ipart[(size_t)ks*64*1024 + m*1024 + gn0 + tx*2 + j] = acc[i][j];
  }
}

__global__ void k_init_red(const float* __restrict__ bh, const float* __restrict__ bc){
  int m = blockIdx.x;
  for (int c=threadIdx.x; c<1024; c+=256){
    float v = g_ipart[m*1024+c] + g_ipart[64*1024 + m*1024+c]
            + g_ipart[2*64*1024 + m*1024+c] + g_ipart[3*64*1024 + m*1024+c];
    if (c < DEC) g_hh[m*DEC + c]      = __float2half_rn(v + bh[c]);
    else         g_c[m*DEC + (c-DEC)] = v + bc[c-DEC];
  }
}

// ---------------- fp16 mma core, double-buffered (M=64, BN=128) ----------------
template<int KLEN>
__device__ __forceinline__ void tc16_core(__half2* sbuf,
    const __half* Ap, const __half* Wp0, const __half* Wp1, float acc[8][4]){
  __half2* sA0 = sbuf;
  __half2* sW0 = sbuf + 2*64*20;
  const int AS = 64*20, WS = 128*20;
  int tid=threadIdx.x, lane=tid&31, wp=tid>>5;
  int mr=wp>>1, nc=wp&1;
  int lr=tid>>2, kq8=(tid&3)*8;
  int r = mr*16 + (lane>>2);
  int cq = lane&3;
  uint4 a  = *(const uint4*)(Ap + kq8);
  uint4 w0 = *(const uint4*)(Wp0 + kq8);
  uint4 w1 = *(const uint4*)(Wp1 + kq8);
  *(uint4*)(sA0 + lr*20 + kq8/2)      = a;
  *(uint4*)(sW0 + lr*20 + kq8/2)      = w0;
  *(uint4*)(sW0 + (lr+64)*20 + kq8/2) = w1;
  __syncthreads();
  for (int k0=0;k0<KLEN;k0+=32){
    int cur = (k0>>5)&1;
    __half2* cA = sA0 + cur*AS;
    __half2* cW = sW0 + cur*WS;
    if (k0+32<KLEN){
      a  = *(const uint4*)(Ap + k0+32 + kq8);
      w0 = *(const uint4*)(Wp0 + k0+32 + kq8);
      w1 = *(const uint4*)(Wp1 + k0+32 + kq8);
      __half2* nA = sA0 + (cur^1)*AS;
      __half2* nW = sW0 + (cur^1)*WS;
      *(uint4*)(nA + lr*20 + kq8/2)      = a;
      *(uint4*)(nW + lr*20 + kq8/2)      = w0;
      *(uint4*)(nW + (lr+64)*20 + kq8/2) = w1;
    }
    #pragma unroll
    for (int kk=0;kk<2;kk++){
      int o = kk*8 + cq;
      uint32_t a0=*(uint32_t*)(cA + r*20 + o);
      uint32_t a1=*(uint32_t*)(cA + (r+8)*20 + o);
      uint32_t a2=*(uint32_t*)(cA + r*20 + o+4);
      uint32_t a3=*(uint32_t*)(cA + (r+8)*20 + o+4);
      #pragma unroll
      for (int j=0;j<8;j++){
        int n = nc*64 + j*8 + (lane>>2);
        uint32_t b0=*(uint32_t*)(cW + n*20 + o);
        uint32_t b1=*(uint32_t*)(cW + n*20 + o+4);
        mma_f16(acc[j], a0, a1, a2, a3, b0, b1);
      }
    }
    __syncthreads();
  }
}
#define SBUF_H2 (2*(64*20 + 128*20))
#define ACC_INIT(acc) { _Pragma("unroll") for (int j=0;j<8;j++){ acc[j][0]=acc[j][1]=acc[j][2]=acc[j][3]=0.f; } }

// one-time: att1 = ench @ W_enc_att^T + bias (fp16 mma). grid (4, 196)
__global__ void __launch_bounds__(256) k_att1(const float* __restrict__ bias){
  __shared__ __align__(16) __half2 sbuf[SBUF_H2];
  int m0 = blockIdx.y*64, gn0 = blockIdx.x*128;
  int tid=threadIdx.x, lane=tid&31, wp=tid>>5;
  int mr=wp>>1, nc=wp&1, lr=tid>>2;
  float acc[8][4]; ACC_INIT(acc)
  tc16_core<ENC>(sbuf,
                 g_ench + (size_t)(m0+lr)*ENC,
                 g_Weah + (size_t)(gn0+lr)*ENC,
                 g_Weah + (size_t)(gn0+lr+64)*ENC, acc);
  int r0=m0+mr*16+(lane>>2), c0=(lane&3)*2;
  #pragma unroll
  for (int j=0;j<8;j++){
    int gn=gn0+nc*64+j*8+c0;
    *(__half2*)(g_att1h + (size_t)r0*ATT + gn)     = __floats2half2_rn(acc[j][0]+bias[gn], acc[j][1]+bias[gn+1]);
    *(__half2*)(g_att1h + (size_t)(r0+8)*ATT + gn) = __floats2half2_rn(acc[j][2]+bias[gn], acc[j][3]+bias[gn+1]);
  }
}

// one-time: g_eg = emb[tok] @ W_ih[:, :512]^T (fp16 mma). grid (16, 31)
__global__ void __launch_bounds__(256) k_embgate(const int* __restrict__ caps){
  __shared__ __align__(16) __half2 sbuf[SBUF_H2];
  int m0 = blockIdx.y*64, gn0 = blockIdx.x*128;
  int tid=threadIdx.x, lane=tid&31, wp=tid>>5;
  int mr=wp>>1, nc=wp&1, lr=tid>>2;
  int gr = m0 + lr;
  int tok = caps[(gr/TSTEPS)*LCAP + (gr%TSTEPS)];
  float acc[8][4]; ACC_INIT(acc)
  tc16_core<EMB>(sbuf,
                 g_embh + (size_t)tok*EMB,
                 g_Wihe + (size_t)(gn0+lr)*EMB,
                 g_Wihe + (size_t)(gn0+lr+64)*EMB, acc);
  int r0=m0+mr*16+(lane>>2), c0=(lane&3)*2;
  #pragma unroll
  for (int j=0;j<8;j++){
    int gn=gn0+nc*64+j*8+c0;
    g_eg[(size_t)r0*G4 + gn]       = acc[j][0];
    g_eg[(size_t)r0*G4 + gn+1]     = acc[j][1];
    g_eg[(size_t)(r0+8)*G4 + gn]   = acc[j][2];
    g_eg[(size_t)(r0+8)*G4 + gn+1] = acc[j][3];
  }
}

// ---------------- per-step kernels ----------------
// ph1: hproj split-K2: 72 tiles; also resets this step's ph3 counter
__global__ void __launch_bounds__(256) k_ph1(int t){
  if (blockIdx.x == 0 && threadIdx.x == 0) g_cnt3[t] = 0;
  __shared__ __align__(16) __half2 sbuf[SBUF_H2];
  int tile = blockIdx.x;
  int nt = tile % 36, ks = tile / 36;
  int gn0 = nt*128, kofs = ks*256;
  int tid=threadIdx.x, lane=tid&31, wp=tid>>5;
  int mr=wp>>1, nc=wp&1, lr=tid>>2;
  float acc[8][4]; ACC_INIT(acc)
  tc16_core<256>(sbuf,
                 g_hh + lr*DEC + kofs,
                 g_Whph + (size_t)(gn0+lr)*DEC + kofs,
                 g_Whph + (size_t)(gn0+lr+64)*DEC + kofs, acc);
  int r0=mr*16+(lane>>2), c0=(lane&3)*2;
  float* out = g_hppart + (size_t)ks*HPS;
  #pragma unroll
  for (int j=0;j<8;j++){
    int gn=gn0+nc*64+j*8+c0;
    out[(size_t)r0*HPN + gn]       = acc[j][0];
    out[(size_t)r0*HPN + gn+1]     = acc[j][1];
    out[(size_t)(r0+8)*HPN + gn]   = acc[j][2];
    out[(size_t)(r0+8)*HPN + gn+1] = acc[j][3];
  }
}

// ph2: alpha+awe (tile = b*2 + half), 256 threads
__global__ void __launch_bounds__(256) k_ph2(
    const float* __restrict__ b_dec_att, const float* __restrict__ w_full,
    const float* __restrict__ b_full, const float* __restrict__ b_beta,
    float* __restrict__ alphas, int t){
  int tile = blockIdx.x;
  int b = tile >> 1, half = tile & 1;
  int tid = threadIdx.x;
  int nact = g_bact[t];
  if (b >= nact){
    if (half == 0)
      for (int p=tid;p<PP;p+=256) alphas[(size_t)b*TSTEPS*PP + (size_t)t*PP + p] = 0.f;
    return;
  }
  __shared__ float s_a2[ATT];
  __shared__ float s_wf[ATT];
  __shared__ float s_e[200];
  __shared__ float s_red[8];
  const float* hp0 = g_hppart + (size_t)b*HPN;
  const float* hp1 = g_hppart + HPS + (size_t)b*HPN;
  for (int a=tid;a<ATT;a+=256){
    s_a2[a] = hp0[a] + hp1[a] + b_dec_att[a];
    s_wf[a] = w_full[a];
  }
  __syncthreads();
  int warp = tid>>5, lane = tid&31;
  float bf = b_full[0];
  for (int p=warp; p<PP; p+=8){
    const __half2* r = (const __half2*)(g_att1h + (size_t)(b*PP+p)*ATT);
    float s=0.f;
    #pragma unroll
    for (int i=0;i<8;i++){
      int a2i = lane + i*32;
      float2 f = __half22float2(r[a2i]);
      int a = a2i*2;
      s += fmaxf(f.x + s_a2[a],0.f)*s_wf[a] + fmaxf(f.y + s_a2[a+1],0.f)*s_wf[a+1];
    }
    #pragma unroll
    for (int o=16;o;o>>=1) s += __shfl_xor_sync(0xffffffffu,s,o);
    if (lane==0) s_e[p] = s + bf;
  }
  __syncthreads();
  float m = (tid < PP) ? s_e[tid] : -1e30f;
  #pragma unroll
  for (int o=16;o;o>>=1) m = fmaxf(m,__shfl_xor_sync(0xffffffffu,m,o));
  if (lane==0) s_red[warp]=m;
  __syncthreads();
  float mx = s_red[0];
  #pragma unroll
  for (int i=1;i<8;i++) mx = fmaxf(mx, s_red[i]);
  __syncthreads();
  float sum = 0.f;
  if (tid < PP){ float ex = expf(s_e[tid]-mx); s_e[tid]=ex; sum=ex; }
  #pragma unroll
  for (int o=16;o;o>>=1) sum += __shfl_xor_sync(0xffffffffu,sum,o);
  if (lane==0) s_red[warp]=sum;
  __syncthreads();
  float tot = 0.f;
  #pragma unroll
  for (int i=0;i<8;i++) tot += s_red[i];
  float inv = 1.0f/tot;
  if (tid < PP){
    float al = s_e[tid]*inv;
    s_e[tid] = al;
    if (half == 0) alphas[(size_t)b*TSTEPS*PP + (size_t)t*PP + tid] = al;
  }
  __syncthreads();
  const __half2* eb = (const __half2*)g_ench + (size_t)b*PP*(ENC/2);
  int c0 = half*512 + tid;
  int c1 = c0 + 256;
  float ax=0.f, ay=0.f, cx=0.f, cy=0.f;
  #pragma unroll 2
  for (int p=0;p<PP;p++){
    float al = s_e[p];
    float2 f0 = __half22float2(eb[(size_t)p*(ENC/2) + c0]);
    float2 f1 = __half22float2(eb[(size_t)p*(ENC/2) + c1]);
    ax += al*f0.x; ay += al*f0.y;
    cx += al*f1.x; cy += al*f1.y;
  }
  int e = c0*2;
  float g0 = sigmoidf_(hp0[ATT+e]   + hp1[ATT+e]   + b_beta[e]);
  float g1 = sigmoidf_(hp0[ATT+e+1] + hp1[ATT+e+1] + b_beta[e+1]);
  *(__half2*)(g_xeh + (size_t)b*ENC + e) = __floats2half2_rn(g0*ax, g1*ay);
  int e2 = c1*2;
  float g2 = sigmoidf_(hp0[ATT+e2]   + hp1[ATT+e2]   + b_beta[e2]);
  float g3 = sigmoidf_(hp0[ATT+e2+1] + hp1[ATT+e2+1] + b_beta[e2+1]);
  *(__half2*)(g_xeh + (size_t)b*ENC + e2) = __floats2half2_rn(g2*cx, g3*cy);
}

// ph3: gates split-K8 (128 tiles) + in-kernel barrier + fused lstm (1 elem/thread)
__global__ void __launch_bounds__(256) k_ph3(const float* __restrict__ b_ih,
                                             const float* __restrict__ b_hh, int t){
  __shared__ __align__(16) __half2 sbuf[SBUF_H2];
  int tile = blockIdx.x;
  int nt = tile & 15, ks = tile >> 4;
  int gn0 = nt*128, kofs = ks*256;
  int tid=threadIdx.x, lane=tid&31, wp=tid>>5;
  int mr=wp>>1, nc=wp&1, lr=tid>>2;
  float acc[8][4]; ACC_INIT(acc)
  tc16_core<256>(sbuf,
                 g_xeh + (size_t)lr*ENC + kofs,
                 g_Wihh + (size_t)(gn0+lr)*ENC + kofs,
                 g_Wihh + (size_t)(gn0+lr+64)*ENC + kofs, acc);
  int r0=mr*16+(lane>>2), c0=(lane&3)*2;
  float* out = g_gpart + (size_t)ks*GS;
  #pragma unroll
  for (int j=0;j<8;j++){
    int gn=gn0+nc*64+j*8+c0;
    out[(size_t)r0*G4 + gn]       = acc[j][0];
    out[(size_t)r0*G4 + gn+1]     = acc[j][1];
    out[(size_t)(r0+8)*G4 + gn]   = acc[j][2];
    out[(size_t)(r0+8)*G4 + gn+1] = acc[j][3];
  }
  // ---- arrival barrier across the 128 co-resident blocks ----
  __syncthreads();
  if (tid == 0){
    __threadfence();
    atomicAdd(&g_cnt3[t], 1);
    while (*(volatile int*)&g_cnt3[t] < 128) __nanosleep(32);
  }
  __syncthreads();
  __threadfence();
  // ---- fused lstm: element idx = blockIdx.x*256 + tid (exactly 64*512) ----
  int idx = tile*256 + tid;
  int b = idx >> 9, j = idx & 511;
  if (b >= g_bact[t]) return;
  const float* eg  = g_eg + ((size_t)b*TSTEPS + t)*G4;
  const float* hp0 = g_hppart + (size_t)b*HPN + ATT + ENC;
  const float* hp1 = g_hppart + HPS + (size_t)b*HPN + ATT + ENC;
  float g[4];
  #pragma unroll
  for (int q=0;q<4;q++){
    int off = q*DEC + j;
    float v = eg[off] + b_ih[off] + b_hh[off] + hp0[off] + hp1[off];
    #pragma unroll
    for (int s=0;s<8;s++) v += g_gpart[(size_t)s*GS + (size_t)b*G4 + off];
    g[q] = v;
  }
  float cn = sigmoidf_(g[1])*g_c[b*DEC+j] + sigmoidf_(g[0])*tanhf(g[2]);
  float hn = sigmoidf_(g[3])*tanhf(cn);
  g_c[b*DEC+j]=cn;
  __half hh = __float2half_rn(hn);
  g_hh[b*DEC+j] = hh;
  g_hhist[((size_t)b*TSTEPS + t)*DEC + j] = hh;
}

// deferred batched fc. grid (157, 31)
__global__ void __launch_bounds__(256) k_fcall(const float* __restrict__ bias,
                                               float* __restrict__ preds){
  __shared__ __align__(16) __half2 sbuf[SBUF_H2];
  int m0 = blockIdx.y*64, gn0 = blockIdx.x*128;
  int tid=threadIdx.x, lane=tid&31, wp=tid>>5;
  int mr=wp>>1, nc=wp&1, lr=tid>>2;
  int wn0 = gn0 + lr;      if (wn0 >= V) wn0 = V-1;
  int wn1 = gn0 + lr + 64; if (wn1 >= V) wn1 = V-1;
  float acc[8][4]; ACC_INIT(acc)
  tc16_core<DEC>(sbuf,
                 g_hhist + (size_t)(m0+lr)*DEC,
                 g_fcWh + (size_t)wn0*DEC, g_fcWh + (size_t)wn1*DEC, acc);
  int r0 = m0 + mr*16 + (lane>>2);
  int r1 = r0 + 8;
  int c0 = (lane&3)*2;
  bool a0 = (r0 / TSTEPS) < g_bact[r0 % TSTEPS];
  bool a1 = (r1 / TSTEPS) < g_bact[r1 % TSTEPS];
  float* row0 = preds + (size_t)r0*V;
  float* row1 = preds + (size_t)r1*V;
  #pragma unroll
  for (int j=0;j<8;j++){
    int gn=gn0+nc*64+j*8+c0;
    if (gn < V){
      row0[gn] = a0 ? (acc[j][0]+bias[gn]) : 0.f;
      row1[gn] = a1 ? (acc[j][2]+bias[gn]) : 0.f;
    }
    if (gn+1 < V){
      row0[gn+1] = a0 ? (acc[j][1]+bias[gn+1]) : 0.f;
      row1[gn+1] = a1 ? (acc[j][3]+bias[gn+1]) : 0.f;
    }
  }
}

// ---------------- launch ----------------
extern "C" void kernel_launch(void* const* d_in, const int* in_sizes, int n_in,
                              void* d_out, int out_size){
  (void)in_sizes; (void)n_in; (void)out_size;
  const float* enc       = (const float*)d_in[0];
  const int*   caps      = (const int*)  d_in[1];
  const int*   caplen    = (const int*)  d_in[2];
  const float* emb_table = (const float*)d_in[3];
  const float* W_enc_att = (const float*)d_in[4];
  const float* b_enc_att = (const float*)d_in[5];
  const float* W_dec_att = (const float*)d_in[6];
  const float* b_dec_att = (const float*)d_in[7];
  const float* w_full    = (const float*)d_in[8];
  const float* b_full    = (const float*)d_in[9];
  const float* W_init_h  = (const float*)d_in[10];
  const float* b_init_h  = (const float*)d_in[11];
  const float* W_init_c  = (const float*)d_in[12];
  const float* b_init_c  = (const float*)d_in[13];
  const float* W_beta    = (const float*)d_in[14];
  const float* b_beta    = (const float*)d_in[15];
  const float* W_ih      = (const float*)d_in[16];
  const float* b_ih      = (const float*)d_in[17];
  const float* W_hh      = (const float*)d_in[18];
  const float* b_hh      = (const float*)d_in[19];
  const float* fc_W      = (const float*)d_in[20];
  const float* fc_b      = (const float*)d_in[21];

  float* preds  = (float*)d_out;                       // [B, T, V]
  float* alphas = preds + (size_t)B*TSTEPS*V;          // [B, T, P]

  k_bact<<<1, 32>>>(caplen);
  k_cvtmean<<<dim3(B, ENC/256), 256>>>(enc);
  k_cvtall<<<(int)((N4_ALL + 255)/256), 256>>>(fc_W, W_enc_att, emb_table,
                                               W_dec_att, W_beta, W_hh, W_ih);
  k_init<<<dim3(32,1,4), 256>>>(W_init_h, W_init_c);
  k_init_red<<<64, 256>>>(b_init_h, b_init_c);
  k_att1<<<dim3(ATT/128, (B*PP)/64), 256>>>(b_enc_att);
  k_embgate<<<dim3(G4/128, NH/64), 256>>>(caps);

  for (int t=0; t<TSTEPS; t++){
    k_ph1<<<72, 256>>>(t);
    k_ph2<<<2*B, 256>>>(b_dec_att, w_full, b_full, b_beta, alphas, t);
    k_ph3<<<128, 256>>>(b_ih, b_hh, t);
  }
  k_fcall<<<dim3((V+127)/128, NH/64), 256>>>(fc_b, preds);
}